// round 8
// baseline (speedup 1.0000x reference)
#include <cuda_runtime.h>
#include <cuda_bf16.h>

// RoIPooling: crop_and_resize bilinear, POOL 7x7.
// feature_map: [B=8, H=64, W=64, C=256] fp32
// roi_bboxes:  [B=8, N=1000, 4] fp32 (y1,x1,y2,x2) normalized
// out:         [B, N, 7, 7, C] fp32
//
// R8: software-rotated px loop with a SINGLE 4xfloat4 data buffer.
// Iteration i: weights(i) + addresses(i+1) computed under the pending
// scoreboard wait for loads(i); loads(i+1) re-issued into the same
// registers immediately after consumption; store last. Keeps data regs
// at 16 (unlike the failed double-buffer R4) while removing the
// address-chain latency from the load-to-load critical path.
// __launch_bounds__(256,7): 36-reg cap, 56 warps/SM (87.5% occ).

namespace {

constexpr int Hc = 64;
constexpr int Wc = 64;
constexpr int Cc = 256;          // channels
constexpr int CQ = Cc / 4;       // 64 float4 per pixel
constexpr int PH = 7;
constexpr int PW = 7;
constexpr int Bc = 8;
constexpr int Nc = 1000;
constexpr int NUM_WARPS = Bc * Nc * PH * 2;     // 112000 (2 channel-halves)
constexpr int WARPS_PER_BLOCK = 8;
constexpr int THREADS = WARPS_PER_BLOCK * 32;

__global__ __launch_bounds__(THREADS, 7) void roi_pool_kernel(
    const float* __restrict__ fm,
    const float* __restrict__ boxes,
    float* __restrict__ out)
{
    const int gwarp = (blockIdx.x * WARPS_PER_BLOCK) + (threadIdx.x >> 5);
    const int lane = threadIdx.x & 31;

    // gwarp = (box * PH + py) * 2 + half   (grid is exact: no bounds guard)
    const int half = gwarp & 1;
    const int row  = gwarp >> 1;       // box * PH + py
    const int py   = row % PH;
    const int box  = row / PH;         // 0 .. B*N-1 (batch-major, matches output)
    const int b    = box / Nc;

    // Box coords (16B aligned)
    const float4 bc = __ldg(reinterpret_cast<const float4*>(boxes) + box);
    const float by1 = bc.x, bx1 = bc.y, by2 = bc.z, bx2 = bc.w;

    const float hm1 = (float)(Hc - 1);
    const float wm1 = (float)(Wc - 1);

    // ---- y math: once per warp (matches reference op order) ----
    const float y = by1 * hm1 + (float)py * ((by2 - by1) * hm1 / (float)(PH - 1));
    const float y0f = floorf(y);
    const float wy  = y - y0f;
    int y0 = (int)y0f;  y0 = min(max(y0, 0), Hc - 1);
    const int y1i = min(y0 + 1, Hc - 1);
    const bool valid_y = (y >= 0.0f) & (y <= hm1);
    const float omwy = 1.0f - wy;

    // quad index within the pixel handled by this lane
    const int q = half * 32 + lane;

    // 32-bit float4 offsets (fm = 8.4M float4, out = 100.4M float4, both < 2^31)
    const float4* fm4 = reinterpret_cast<const float4*>(fm);
    const int bbase   = b * (Hc * Wc * CQ);
    const int rowT    = bbase + y0  * (Wc * CQ) + q;   // top row, this lane's quad
    const int rowB    = bbase + y1i * (Wc * CQ) + q;   // bottom row

    // ---- x constants: once per warp ----
    const float xbase = bx1 * wm1;
    const float dx    = (bx2 - bx1) * wm1 / (float)(PW - 1);

    unsigned int oofs = (unsigned int)row * (PW * CQ) + q;
    float4* o4 = reinterpret_cast<float4*>(out);

    // per-px x math (same op order as reference)
    auto xmath = [&](int px, int& x0q, int& x1q, float& wx, float& m) {
        const float xv = xbase + (float)px * dx;
        const float xf = floorf(xv);
        wx = xv - xf;
        int xi = (int)xf;  xi = min(max(xi, 0), Wc - 1);
        x0q = xi * CQ;
        x1q = min(xi + 1, Wc - 1) * CQ;
        m = (valid_y & (xv >= 0.0f) & (xv <= wm1)) ? 1.0f : 0.0f;
    };

    // ---- prologue: px = 0 addresses + loads ----
    int   x0q, x1q;
    float wx, m;
    xmath(0, x0q, x1q, wx, m);

    float4 a = __ldg(fm4 + rowT + x0q);
    float4 bq= __ldg(fm4 + rowT + x1q);
    float4 c = __ldg(fm4 + rowB + x0q);
    float4 d = __ldg(fm4 + rowB + x1q);

    #pragma unroll 1
    for (int px = 0; px < PW; ++px) {
        // weights for current px (runs under the pending load wait)
        const float omwx = 1.0f - wx;
        const float w00 = omwx * omwy * m;
        const float w01 = wx   * omwy * m;
        const float w10 = omwx * wy   * m;
        const float w11 = wx   * wy   * m;

        // next px addresses (also under the pending load wait)
        const bool more = (px < PW - 1);
        int nx0q = x0q, nx1q = x1q;
        float nwx = wx, nm = m;
        if (more) xmath(px + 1, nx0q, nx1q, nwx, nm);

        // consume current loads
        float4 r;
        r.x = fmaf(a.x, w00, fmaf(bq.x, w01, fmaf(c.x, w10, d.x * w11)));
        r.y = fmaf(a.y, w00, fmaf(bq.y, w01, fmaf(c.y, w10, d.y * w11)));
        r.z = fmaf(a.z, w00, fmaf(bq.z, w01, fmaf(c.z, w10, d.z * w11)));
        r.w = fmaf(a.w, w00, fmaf(bq.w, w01, fmaf(c.w, w10, d.w * w11)));

        // immediately re-issue next loads into the SAME registers
        if (more) {
            a = __ldg(fm4 + rowT + nx0q);
            bq= __ldg(fm4 + rowT + nx1q);
            c = __ldg(fm4 + rowB + nx0q);
            d = __ldg(fm4 + rowB + nx1q);
        }

        // rotate scalars
        x0q = nx0q; x1q = nx1q; wx = nwx; m = nm;

        // Streaming store: keep the 401MB output stream from evicting the
        // 33.5MB feature map out of L2 (gathers depend on L2 hits).
        __stcs(o4 + oofs, r);
        oofs += CQ;
    }
}

} // namespace

extern "C" void kernel_launch(void* const* d_in, const int* in_sizes, int n_in,
                              void* d_out, int out_size) {
    const float* fm    = (const float*)d_in[0];
    const float* boxes = (const float*)d_in[1];
    float* out         = (float*)d_out;

    const int blocks = NUM_WARPS / WARPS_PER_BLOCK;  // 14000, exact
    roi_pool_kernel<<<blocks, THREADS>>>(fm, boxes, out);
}

// round 9
// speedup vs baseline: 5.7031x; 5.7031x over previous
#include <cuda_runtime.h>
#include <cuda_bf16.h>

// RoIPooling: crop_and_resize bilinear, POOL 7x7.
// feature_map: [B=8, H=64, W=64, C=256] fp32
// roi_bboxes:  [B=8, N=1000, 4] fp32 (y1,x1,y2,x2) normalized
// out:         [B, N, 7, 7, C] fp32
//
// R9: lane remap. One warp per (box, py, px-quadrant): lanes = 4 px-groups
// x 8 channel lanes. Each lane owns one px; its bilinear weights/offsets are
// computed ONCE in the preamble. Inner loop over 8 channel chunks is pure
// 4xLDG + 16 FFMA + STG + constant-offset IADDs — no dependent scalar math
// between load batches. Per-LDG: 4 full 128B lines (100% utilization, 4 wf),
// same wavefront floor as R3 but ~2x fewer non-memory instructions per wf.

namespace {

constexpr int Hc = 64;
constexpr int Wc = 64;
constexpr int Cc = 256;          // channels
constexpr int CQ = Cc / 4;       // 64 float4 per pixel
constexpr int PH = 7;
constexpr int PW = 7;
constexpr int Bc = 8;
constexpr int Nc = 1000;
constexpr int ROWS = Bc * Nc * PH;              // 56000 (box,py) rows
constexpr int NUM_WARPS = ROWS * 2;             // 112000 (2 px-quadrants)
constexpr int WARPS_PER_BLOCK = 8;
constexpr int THREADS = WARPS_PER_BLOCK * 32;
constexpr int WCQ = Wc * CQ;

__global__ __launch_bounds__(THREADS, 8) void roi_pool_kernel(
    const float* __restrict__ fm,
    const float* __restrict__ boxes,
    float* __restrict__ out)
{
    const int gwarp = (blockIdx.x * WARPS_PER_BLOCK) + (threadIdx.x >> 5);
    const int lane = threadIdx.x & 31;

    // gwarp = row * 2 + wsel ; row = box*PH + py
    const int wsel = gwarp & 1;
    const int row  = gwarp >> 1;
    const int py   = row % PH;
    const int box  = row / PH;         // 0 .. B*N-1 (batch-major, matches output)
    const int b    = box / Nc;

    // lane mapping: pg = px group (0..3), sub = channel lane (0..7)
    const int pg  = lane >> 3;
    const int sub = lane & 7;
    const int pxr = wsel * 4 + pg;                 // 0..7 (7 = idle group)
    const bool live = (pxr < PW);
    const int px  = live ? pxr : (PW - 1);         // idle lanes alias px=6

    // Box coords (16B aligned)
    const float4 bc = __ldg(reinterpret_cast<const float4*>(boxes) + box);
    const float by1 = bc.x, bx1 = bc.y, by2 = bc.z, bx2 = bc.w;

    const float hm1 = (float)(Hc - 1);
    const float wm1 = (float)(Wc - 1);

    // ---- y math (warp-uniform, matches reference op order) ----
    const float y = by1 * hm1 + (float)py * ((by2 - by1) * hm1 / (float)(PH - 1));
    const float y0f = floorf(y);
    const float wy  = y - y0f;
    int y0 = (int)y0f;  y0 = min(max(y0, 0), Hc - 1);
    const int y1i = min(y0 + 1, Hc - 1);
    const bool valid_y = (y >= 0.0f) & (y <= hm1);
    const float omwy = 1.0f - wy;

    // ---- x math for THIS lane's px (once; lives in registers) ----
    const float xbase = bx1 * wm1;
    const float dx    = (bx2 - bx1) * wm1 / (float)(PW - 1);
    const float xv  = xbase + (float)px * dx;      // same op order as reference
    const float xf  = floorf(xv);
    const float wx  = xv - xf;
    int xi = (int)xf;  xi = min(max(xi, 0), Wc - 1);
    const int x1c = min(xi + 1, Wc - 1);
    const float m = (valid_y & (xv >= 0.0f) & (xv <= wm1)) ? 1.0f : 0.0f;

    // corner weights, validity folded in (m==0 -> exact zero output)
    const float omwx = 1.0f - wx;
    const float w00 = omwx * omwy * m;
    const float w01 = wx   * omwy * m;
    const float w10 = omwx * wy   * m;
    const float w11 = wx   * wy   * m;

    // ---- per-lane float4 offsets (32-bit; fm=8.4M, out=100.4M float4) ----
    const float4* fm4 = reinterpret_cast<const float4*>(fm);
    const int bbase = b * (Hc * WCQ);
    int oT0 = bbase + y0  * WCQ + xi  * CQ + sub;   // top-left
    int oT1 = bbase + y0  * WCQ + x1c * CQ + sub;   // top-right
    int oB0 = bbase + y1i * WCQ + xi  * CQ + sub;   // bottom-left
    int oB1 = bbase + y1i * WCQ + x1c * CQ + sub;   // bottom-right

    // output offset: row*(PW*CQ) + px*CQ + sub
    unsigned int oofs = (unsigned int)row * (PW * CQ) + px * CQ + sub;
    float4* o4 = reinterpret_cast<float4*>(out);

    #pragma unroll 1
    for (int k = 0; k < CQ / 8; ++k) {
        // 4 corner loads: each covers 4 full 128B lines (one per px group)
        const float4 a = __ldg(fm4 + oT0);
        const float4 bq= __ldg(fm4 + oT1);
        const float4 c = __ldg(fm4 + oB0);
        const float4 d = __ldg(fm4 + oB1);

        float4 r;
        r.x = fmaf(a.x, w00, fmaf(bq.x, w01, fmaf(c.x, w10, d.x * w11)));
        r.y = fmaf(a.y, w00, fmaf(bq.y, w01, fmaf(c.y, w10, d.y * w11)));
        r.z = fmaf(a.z, w00, fmaf(bq.z, w01, fmaf(c.z, w10, d.z * w11)));
        r.w = fmaf(a.w, w00, fmaf(bq.w, w01, fmaf(c.w, w10, d.w * w11)));

        // Streaming store (keep the 401MB output stream from evicting the
        // 33.5MB feature map out of L2). Idle px-group lanes skip the store.
        if (live) __stcs(o4 + oofs, r);

        oT0 += 8; oT1 += 8; oB0 += 8; oB1 += 8;
        oofs += 8;
    }
}

} // namespace

extern "C" void kernel_launch(void* const* d_in, const int* in_sizes, int n_in,
                              void* d_out, int out_size) {
    const float* fm    = (const float*)d_in[0];
    const float* boxes = (const float*)d_in[1];
    float* out         = (float*)d_out;

    const int blocks = NUM_WARPS / WARPS_PER_BLOCK;  // 14000, exact
    roi_pool_kernel<<<blocks, THREADS>>>(fm, boxes, out);
}

// round 10
// speedup vs baseline: 6.8640x; 1.2036x over previous
#include <cuda_runtime.h>
#include <cuda_bf16.h>

// RoIPooling: crop_and_resize bilinear, POOL 7x7.
// feature_map: [B=8, H=64, W=64, C=256] fp32
// roi_bboxes:  [B=8, N=1000, 4] fp32 (y1,x1,y2,x2) normalized
// out:         [B, N, 7, 7, C] fp32
//
// R10: R7 body unchanged (proven local optimum: one warp per
// (box,py,channel-half), weight-form bilinear, 4-corner LDG.128 batch,
// 32 regs) with CTA size 128 instead of 256: 16 CTAs/SM at the same
// 64 warps/SM. Finer CTA granularity reduces cross-CTA L1tex queue
// burstiness and wave-tail imbalance — the last identified slack on the
// L1-wavefront-bound roofline (~58us floor, R7 at 80%).

namespace {

constexpr int Hc = 64;
constexpr int Wc = 64;
constexpr int Cc = 256;          // channels
constexpr int CQ = Cc / 4;       // 64 float4 per pixel
constexpr int PH = 7;
constexpr int PW = 7;
constexpr int Bc = 8;
constexpr int Nc = 1000;
constexpr int NUM_WARPS = Bc * Nc * PH * 2;     // 112000 (2 channel-halves)
constexpr int WARPS_PER_BLOCK = 4;
constexpr int THREADS = WARPS_PER_BLOCK * 32;   // 128

__global__ __launch_bounds__(THREADS, 16) void roi_pool_kernel(
    const float* __restrict__ fm,
    const float* __restrict__ boxes,
    float* __restrict__ out)
{
    const int gwarp = (blockIdx.x * WARPS_PER_BLOCK) + (threadIdx.x >> 5);
    const int lane = threadIdx.x & 31;

    // gwarp = (box * PH + py) * 2 + half   (grid is exact: no bounds guard)
    const int half = gwarp & 1;
    const int row  = gwarp >> 1;       // box * PH + py
    const int py   = row % PH;
    const int box  = row / PH;         // 0 .. B*N-1 (batch-major, matches output)
    const int b    = box / Nc;

    // Box coords (16B aligned)
    const float4 bc = __ldg(reinterpret_cast<const float4*>(boxes) + box);
    const float by1 = bc.x, bx1 = bc.y, by2 = bc.z, bx2 = bc.w;

    const float hm1 = (float)(Hc - 1);
    const float wm1 = (float)(Wc - 1);

    // ---- y math: once per warp (matches reference op order) ----
    const float y = by1 * hm1 + (float)py * ((by2 - by1) * hm1 / (float)(PH - 1));
    const float y0f = floorf(y);
    const float wy  = y - y0f;
    int y0 = (int)y0f;  y0 = min(max(y0, 0), Hc - 1);
    const int y1i = min(y0 + 1, Hc - 1);
    const bool valid_y = (y >= 0.0f) & (y <= hm1);
    const float omwy = 1.0f - wy;

    // quad index within the pixel handled by this lane
    const int q = half * 32 + lane;

    // 32-bit float4 offsets (fm = 8.4M float4, out = 100.4M float4, both < 2^31)
    const float4* fm4 = reinterpret_cast<const float4*>(fm);
    const int bbase   = b * (Hc * Wc * CQ);
    const int rowT    = bbase + y0  * (Wc * CQ) + q;   // top row, this lane's quad
    const int rowB    = bbase + y1i * (Wc * CQ) + q;   // bottom row

    // ---- x constants: once per warp ----
    const float xbase = bx1 * wm1;
    const float dx    = (bx2 - bx1) * wm1 / (float)(PW - 1);

    unsigned int oofs = (unsigned int)row * (PW * CQ) + q;
    float4* o4 = reinterpret_cast<float4*>(out);

    #pragma unroll 1
    for (int px = 0; px < PW; ++px) {
        const float x   = xbase + (float)px * dx;   // same op order as reference
        const float x0f = floorf(x);
        const float wx  = x - x0f;
        int x0 = (int)x0f;  x0 = min(max(x0, 0), Wc - 1);
        const int x1i = min(x0 + 1, Wc - 1);
        const float m = (valid_y & (x >= 0.0f) & (x <= wm1)) ? 1.0f : 0.0f;

        // Corner weights (warp-uniform per px), mask folded in.
        // m==0 -> all weights 0 -> r == 0 exactly.
        const float omwx = 1.0f - wx;
        const float w00 = omwx * omwy * m;   // a: (y0, x0)
        const float w01 = wx   * omwy * m;   // b: (y0, x1)
        const float w10 = omwx * wy   * m;   // c: (y1, x0)
        const float w11 = wx   * wy   * m;   // d: (y1, x1)

        const int x0q = x0  * CQ;
        const int x1q = x1i * CQ;

        // Front-batch the 4 corner loads (MLP = 4, 16 warps/SMSP resident)
        const float4 a = __ldg(fm4 + rowT + x0q);
        const float4 bq= __ldg(fm4 + rowT + x1q);
        const float4 c = __ldg(fm4 + rowB + x0q);
        const float4 d = __ldg(fm4 + rowB + x1q);

        float4 r;
        r.x = fmaf(a.x, w00, fmaf(bq.x, w01, fmaf(c.x, w10, d.x * w11)));
        r.y = fmaf(a.y, w00, fmaf(bq.y, w01, fmaf(c.y, w10, d.y * w11)));
        r.z = fmaf(a.z, w00, fmaf(bq.z, w01, fmaf(c.z, w10, d.z * w11)));
        r.w = fmaf(a.w, w00, fmaf(bq.w, w01, fmaf(c.w, w10, d.w * w11)));

        // Streaming store: keep the 401MB output stream from evicting the
        // 33.5MB feature map out of L2 (gathers depend on L2 hits).
        __stcs(o4 + oofs, r);
        oofs += CQ;
    }
}

} // namespace

extern "C" void kernel_launch(void* const* d_in, const int* in_sizes, int n_in,
                              void* d_out, int out_size) {
    const float* fm    = (const float*)d_in[0];
    const float* boxes = (const float*)d_in[1];
    float* out         = (float*)d_out;

    const int blocks = NUM_WARPS / WARPS_PER_BLOCK;  // 28000, exact
    roi_pool_kernel<<<blocks, THREADS>>>(fm, boxes, out);
}